// round 9
// baseline (speedup 1.0000x reference)
#include <cuda_runtime.h>
#include <cuda_fp16.h>
#include <cstdint>
#include <cstddef>

// ---------------- problem constants ----------------
#define NMOD 5
#define MAXB 65536

// ---------------- static scratch (device symbols) ----------------
__device__ __half g_xqkvh[(size_t)MAXB * NMOD * 512];          // [B][5][x|q|k|v] fp16
__device__ __half g_yh[(size_t)MAXB * 640];                    // post-LN (fp16)
__device__ __half g_eh[(size_t)MAXB * 992 + 640 * 992];        // fp16 embeddings + fus_w
__device__ __half g_W1h[512 * 992];                            // merged modality weights (fp16)
__device__ float  g_b1[NMOD * 512];                            // merged biases (fp32)

// ---------------- helpers ----------------
__device__ __forceinline__ void mma_f16(float c[4], const uint32_t a[4],
                                        uint32_t b0, uint32_t b1) {
    asm volatile(
        "mma.sync.aligned.m16n8k16.row.col.f32.f16.f16.f32 "
        "{%0,%1,%2,%3},{%4,%5,%6,%7},{%8,%9},{%0,%1,%2,%3};"
        : "+f"(c[0]), "+f"(c[1]), "+f"(c[2]), "+f"(c[3])
        : "r"(a[0]), "r"(a[1]), "r"(a[2]), "r"(a[3]), "r"(b0), "r"(b1));
}
__device__ __forceinline__ void ldsm4(uint32_t& r0, uint32_t& r1, uint32_t& r2,
                                      uint32_t& r3, uint32_t addr) {
    asm volatile("ldmatrix.sync.aligned.m8n8.x4.shared.b16 {%0,%1,%2,%3}, [%4];"
                 : "=r"(r0), "=r"(r1), "=r"(r2), "=r"(r3) : "r"(addr));
}
__device__ __forceinline__ uint32_t smem_u32(const void* p) {
    uint32_t a;
    asm("{ .reg .u64 t; cvta.to.shared.u64 t, %1; cvt.u32.u64 %0, t; }" : "=r"(a) : "l"(p));
    return a;
}
__device__ __forceinline__ void cp16(uint32_t dst, const void* src, bool v) {
    asm volatile("cp.async.cg.shared.global [%0], [%1], 16, %2;"
                 :: "r"(dst), "l"(src), "r"(v ? 16u : 0u));
}
#define CP_COMMIT() asm volatile("cp.async.commit_group;" ::: "memory")
#define CP_WAIT1()  asm volatile("cp.async.wait_group 1;" ::: "memory")
#define CP_WAIT0()  asm volatile("cp.async.wait_group 0;" ::: "memory")

// ---------------- cvt: fp32 -> fp16 for embeddings + fus_w ----------------
struct CvtParams {
    const float* src[6];
    size_t off[6];
    int n[6];
};
__global__ void cvt_kernel(CvtParams p) {
    int m = blockIdx.y;
    int idx = (blockIdx.x * 256 + threadIdx.x) * 8;
    if (idx >= p.n[m]) return;
    const float4* s = reinterpret_cast<const float4*>(p.src[m] + idx);
    float4 a = s[0], b = s[1];
    __half2 h0 = __floats2half2_rn(a.x, a.y);
    __half2 h1 = __floats2half2_rn(a.z, a.w);
    __half2 h2 = __floats2half2_rn(b.x, b.y);
    __half2 h3 = __floats2half2_rn(b.z, b.w);
    uint4 o;
    o.x = *reinterpret_cast<uint32_t*>(&h0);
    o.y = *reinterpret_cast<uint32_t*>(&h1);
    o.z = *reinterpret_cast<uint32_t*>(&h2);
    o.w = *reinterpret_cast<uint32_t*>(&h3);
    *reinterpret_cast<uint4*>(g_eh + p.off[m] + idx) = o;
}

// ---------------- prep: merged weights (fp16) + biases (fp32) ----------------
__global__ void prep_all_kernel(
    const float* __restrict__ Wc, const float* __restrict__ bc,
    const float* __restrict__ Wm, const float* __restrict__ bm,
    const float* __restrict__ Wd, const float* __restrict__ bd,
    const float* __restrict__ Wp, const float* __restrict__ bp,
    const float* __restrict__ Wr, const float* __restrict__ br,
    const float* __restrict__ in_w, const float* __restrict__ in_b) {
    int m = blockIdx.y;
    const float* Wmod; const float* bmod; int K; int off;
    switch (m) {
        case 0: Wmod = Wc; bmod = bc; K = 128; off = 0; break;
        case 1: Wmod = Wm; bmod = bm; K = 256; off = 512 * 128; break;
        case 2: Wmod = Wd; bmod = bd; K = 64;  off = 512 * 384; break;
        case 3: Wmod = Wp; bmod = bp; K = 32;  off = 512 * 448; break;
        default: Wmod = Wr; bmod = br; K = 512; off = 512 * 480; break;
    }
    int w = blockIdx.x * 256 + threadIdx.x;
    if (w >= 512 * K) return;
    int part = w & 3;
    int q = w >> 2;
    int K4 = K >> 2;
    int j = q / K4;
    int k4 = (q - j * K4) * 4;
    float4 acc = make_float4(0.f, 0.f, 0.f, 0.f);
    if (j < 128) {
        if (part == 0) acc = *reinterpret_cast<const float4*>(Wmod + (size_t)j * K + k4);
    } else {
        const float* iw = in_w + (size_t)(j - 128) * 128 + part * 32;
        const float* wp = Wmod + (size_t)(part * 32) * K + k4;
#pragma unroll 8
        for (int t = 0; t < 32; t++) {
            float wv = iw[t];
            float4 v = *reinterpret_cast<const float4*>(wp + (size_t)t * K);
            acc.x += wv * v.x; acc.y += wv * v.y; acc.z += wv * v.z; acc.w += wv * v.w;
        }
    }
#pragma unroll
    for (int d = 1; d <= 2; d <<= 1) {
        acc.x += __shfl_xor_sync(0xffffffffu, acc.x, d);
        acc.y += __shfl_xor_sync(0xffffffffu, acc.y, d);
        acc.z += __shfl_xor_sync(0xffffffffu, acc.z, d);
        acc.w += __shfl_xor_sync(0xffffffffu, acc.w, d);
    }
    if (part == 0) {
        __half2 h0 = __floats2half2_rn(acc.x, acc.y);
        __half2 h1 = __floats2half2_rn(acc.z, acc.w);
        *reinterpret_cast<uint2*>(g_W1h + off + (size_t)j * K + k4) =
            make_uint2(*reinterpret_cast<uint32_t*>(&h0), *reinterpret_cast<uint32_t*>(&h1));
        if (k4 == 0) {
            float bb;
            if (j < 128) bb = bmod[j];
            else {
                const float* iw2 = in_w + (size_t)(j - 128) * 128;
                float a = in_b[j - 128];
                for (int t = 0; t < 128; t++) a += iw2[t] * bmod[t];
                bb = a;
            }
            g_b1[m * 512 + j] = bb;
        }
    }
}

// ---------------- fp16 cp.async GEMM core (ldmatrix frags, 1 barrier/ktile) ----------------
#define BK 64
#define ROWH 72
#define ROWWD 36
#define STAGE_H (256 * ROWH)
#define STAGE_B (STAGE_H * 2)
#define NSTAGE 3
#define GEMM_SMEM (NSTAGE * STAGE_B)     // 110592 bytes

__device__ __forceinline__ void gemm_core(
    const __half* __restrict__ Ablk, int lda,
    const __half* __restrict__ W, int ldw,
    const float* __restrict__ bias,
    float* outf, __half* outh, int ldo,
    int N, int K, int Mbase, int nbase,
    uint32_t shu) {

    int tid = threadIdx.x, warp = tid >> 5, lane = tid & 31;
    int wm = warp >> 2, wn = warp & 3;
    int nkt = (K + BK - 1) / BK;

    float acc[4][4][4];
#pragma unroll
    for (int i = 0; i < 4; i++)
#pragma unroll
        for (int j = 0; j < 4; j++)
#pragma unroll
            for (int q = 0; q < 4; q++) acc[i][j][q] = 0.f;

    auto load_stage = [&](int kt, int st) {
        int k0 = kt * BK;
        uint32_t dbase = shu + st * STAGE_B;
#pragma unroll
        for (int i = 0; i < 8; i++) {
            int c = tid + (i << 8);
            int row = c >> 3, seg = c & 7;
            int kk = k0 + seg * 8;
            const __half* src;
            bool v;
            if (row < 128) {
                v = kk < K;
                src = v ? (Ablk + (size_t)row * lda + kk) : Ablk;
            } else {
                int n = row - 128;
                v = (nbase + n < N) && (kk < K);
                src = v ? (W + (size_t)(nbase + n) * ldw + kk) : W;
            }
            cp16(dbase + (uint32_t)(row * ROWH + seg * 8) * 2, src, v);
        }
        CP_COMMIT();
    };

    load_stage(0, 0);
    if (nkt > 1) load_stage(1, 1);

    // per-lane ldmatrix byte offsets within a stage
    uint32_t aoffb = ((uint32_t)((wm * 64 + (lane & 15)) * ROWWD + ((lane >> 4) << 2))) << 2;
    uint32_t boffb = ((uint32_t)((128 + wn * 32 + (((lane >> 4) & 1) << 3) + (lane & 7)) * ROWWD
                                 + (((lane >> 3) & 1) << 2))) << 2;

    for (int kt = 0; kt < nkt; kt++) {
        int st = kt % 3;
        // stage kt is the (kt+1)-th committed group; groups committed so far = min(nkt, kt+2)
        if (kt + 1 < nkt) { CP_WAIT1(); } else { CP_WAIT0(); }
        __syncthreads();                       // single barrier per ktile: orders WAR + visibility
        if (kt + 2 < nkt) load_stage(kt + 2, (kt + 2) % 3);

        uint32_t sb = shu + st * STAGE_B;
#pragma unroll
        for (int ks = 0; ks < 4; ks++) {
            uint32_t kb = sb + ks * 32;
            uint32_t af[4][4];
#pragma unroll
            for (int mf = 0; mf < 4; mf++)
                ldsm4(af[mf][0], af[mf][1], af[mf][2], af[mf][3],
                      kb + aoffb + mf * (16 * ROWWD * 4));
            uint32_t p0[4], p1[4];
            ldsm4(p0[0], p0[1], p0[2], p0[3], kb + boffb);
            ldsm4(p1[0], p1[1], p1[2], p1[3], kb + boffb + 16 * ROWWD * 4);
#pragma unroll
            for (int mf = 0; mf < 4; mf++) {
                mma_f16(acc[mf][0], af[mf], p0[0], p0[1]);
                mma_f16(acc[mf][1], af[mf], p0[2], p0[3]);
                mma_f16(acc[mf][2], af[mf], p1[0], p1[1]);
                mma_f16(acc[mf][3], af[mf], p1[2], p1[3]);
            }
        }
    }

    int lr = lane >> 2, lc = lane & 3;
    if (outh) {
#pragma unroll
        for (int mf = 0; mf < 4; mf++) {
            int row0 = Mbase + wm * 64 + mf * 16 + lr;
#pragma unroll
            for (int nf = 0; nf < 4; nf++) {
                int col = nbase + wn * 32 + nf * 8 + lc * 2;
                if (col < N) {
                    float2 bv = *reinterpret_cast<const float2*>(bias + col);
                    __half2 h0 = __floats2half2_rn(acc[mf][nf][0] + bv.x, acc[mf][nf][1] + bv.y);
                    __half2 h1 = __floats2half2_rn(acc[mf][nf][2] + bv.x, acc[mf][nf][3] + bv.y);
                    *reinterpret_cast<uint32_t*>(outh + (size_t)row0 * ldo + col) =
                        *reinterpret_cast<uint32_t*>(&h0);
                    *reinterpret_cast<uint32_t*>(outh + (size_t)(row0 + 8) * ldo + col) =
                        *reinterpret_cast<uint32_t*>(&h1);
                }
            }
        }
    } else {
#pragma unroll
        for (int mf = 0; mf < 4; mf++) {
            int row0 = Mbase + wm * 64 + mf * 16 + lr;
#pragma unroll
            for (int nf = 0; nf < 4; nf++) {
                int col = nbase + wn * 32 + nf * 8 + lc * 2;
                if (col < N) {
                    float2 bv = *reinterpret_cast<const float2*>(bias + col);
                    float2 v0 = make_float2(acc[mf][nf][0] + bv.x, acc[mf][nf][1] + bv.y);
                    float2 v1 = make_float2(acc[mf][nf][2] + bv.x, acc[mf][nf][3] + bv.y);
                    *reinterpret_cast<float2*>(outf + (size_t)row0 * ldo + col) = v0;
                    *reinterpret_cast<float2*>(outf + (size_t)(row0 + 8) * ldo + col) = v1;
                }
            }
        }
    }
}

struct GemmAParams {
    size_t aoff[5];
    int K[5];
    int woff[5];
};

// grid: (x = N-tile(4), y = M-tile, z = modality); output fp16 into g_xqkvh
__global__ void __launch_bounds__(256, 2) gemmA_kernel(GemmAParams p) {
    extern __shared__ __half sh[];
    int m = blockIdx.z;
    int Mbase = blockIdx.y * 128, nbase = blockIdx.x * 128;
    gemm_core(g_eh + p.aoff[m] + (size_t)Mbase * p.K[m], p.K[m],
              g_W1h + p.woff[m], p.K[m], g_b1 + m * 512,
              nullptr, g_xqkvh + m * 512, NMOD * 512, 512, p.K[m],
              Mbase, nbase, smem_u32(sh));
}

// grid: (x = N-tile(8), y = M-tile)
__global__ void __launch_bounds__(256, 2) gemmF_kernel(
    size_t fw_off, const float* __restrict__ fus_b, float* __restrict__ out) {
    extern __shared__ __half sh[];
    int Mbase = blockIdx.y * 128, nbase = blockIdx.x * 128;
    gemm_core(g_yh + (size_t)Mbase * 640, 640,
              g_eh + fw_off, 640, fus_b,
              out, nullptr, 992, 992, 640, Mbase, nbase, smem_u32(sh));
}

// ---------------- fused attention + out-proj + residual + LayerNorm ----------------
#define AROWW 68                                  // words per smem row (136 halves)
#define ATTN_SMEM ((160 + 128) * AROWW * 4)       // 78336 bytes

__global__ void __launch_bounds__(256, 2) attn_kernel(
    const float* __restrict__ out_w, const float* __restrict__ out_b,
    const float* __restrict__ ln_g, const float* __restrict__ ln_b) {
    extern __shared__ uint32_t smw[];
    uint32_t* s_ctx = smw;                 // [160][AROWW] words (fp16 ctx)
    uint32_t* s_w = smw + 160 * AROWW;     // [128][AROWW] words (fp16 out_w)

    int tid = threadIdx.x, warp = tid >> 5, lane = tid & 31;
    int S0 = blockIdx.x * 32;
    uint32_t ctx_u = smem_u32(s_ctx);
    uint32_t w_u = smem_u32(s_w);

    // stage out_w -> fp16 smem
    for (int idx = tid; idx < 128 * 16; idx += 256) {
        int r = idx >> 4;
        int c8 = (idx & 15) * 8;
        const float4* p = reinterpret_cast<const float4*>(out_w + (size_t)r * 128 + c8);
        float4 a = p[0], b = p[1];
        __half2 h0 = __floats2half2_rn(a.x, a.y);
        __half2 h1 = __floats2half2_rn(a.z, a.w);
        __half2 h2 = __floats2half2_rn(b.x, b.y);
        __half2 h3 = __floats2half2_rn(b.z, b.w);
        uint4 o;
        o.x = *reinterpret_cast<uint32_t*>(&h0);
        o.y = *reinterpret_cast<uint32_t*>(&h1);
        o.z = *reinterpret_cast<uint32_t*>(&h2);
        o.w = *reinterpret_cast<uint32_t*>(&h3);
        *reinterpret_cast<uint4*>(s_w + r * AROWW + (c8 >> 1)) = o;
    }

    // softmax + ctx (fp16 inputs, fp32 math), 4 samples per warp
#pragma unroll
    for (int t = 0; t < 4; t++) {
        int sl = warp * 4 + t;
        int s = S0 + sl;
        const __half* rb = g_xqkvh + (size_t)s * (NMOD * 512);
        float attn[5] = {0.f, 0.f, 0.f, 0.f, 0.f};
        if (lane < 20) {
            int h = lane / 5, i = lane % 5;
            float qv[32];
            {
                const uint4* qp = reinterpret_cast<const uint4*>(rb + i * 512 + 128 + h * 32);
#pragma unroll
                for (int u = 0; u < 4; u++) {
                    uint4 w = qp[u];
                    const uint32_t ww[4] = {w.x, w.y, w.z, w.w};
#pragma unroll
                    for (int e = 0; e < 4; e++) {
                        float2 f = __half22float2(*reinterpret_cast<const __half2*>(&ww[e]));
                        qv[u * 8 + e * 2] = f.x; qv[u * 8 + e * 2 + 1] = f.y;
                    }
                }
            }
            float sc[5];
#pragma unroll
            for (int j = 0; j < 5; j++) {
                const uint4* kp = reinterpret_cast<const uint4*>(rb + j * 512 + 256 + h * 32);
                float a = 0.f;
#pragma unroll
                for (int u = 0; u < 4; u++) {
                    uint4 w = kp[u];
                    const uint32_t ww[4] = {w.x, w.y, w.z, w.w};
#pragma unroll
                    for (int e = 0; e < 4; e++) {
                        float2 f = __half22float2(*reinterpret_cast<const __half2*>(&ww[e]));
                        a += qv[u * 8 + e * 2] * f.x + qv[u * 8 + e * 2 + 1] * f.y;
                    }
                }
                sc[j] = a * 0.17677669529663687f;   // 1/sqrt(32)
            }
            float mx = sc[0];
#pragma unroll
            for (int j = 1; j < 5; j++) mx = fmaxf(mx, sc[j]);
            float den = 0.f;
#pragma unroll
            for (int j = 0; j < 5; j++) { attn[j] = __expf(sc[j] - mx); den += attn[j]; }
            float inv = 1.f / den;
#pragma unroll
            for (int j = 0; j < 5; j++) attn[j] *= inv;
        }
        __syncwarp();
        int h2 = lane >> 3;
#pragma unroll
        for (int i = 0; i < 5; i++) {
            float a0 = 0.f, a1 = 0.f, a2 = 0.f, a3 = 0.f;
#pragma unroll
            for (int j = 0; j < 5; j++) {
                float a = __shfl_sync(0xffffffffu, attn[j], h2 * 5 + i);
                uint2 w = *reinterpret_cast<const uint2*>(rb + j * 512 + 384 + lane * 4);
                float2 f0 = __half22float2(*reinterpret_cast<const __half2*>(&w.x));
                float2 f1 = __half22float2(*reinterpret_cast<const __half2*>(&w.y));
                a0 += a * f0.x; a1 += a * f0.y; a2 += a * f1.x; a3 += a * f1.y;
            }
            __half2 h0 = __floats2half2_rn(a0, a1);
            __half2 h1 = __floats2half2_rn(a2, a3);
            *reinterpret_cast<uint2*>(s_ctx + (sl * 5 + i) * AROWW + lane * 2) =
                make_uint2(*reinterpret_cast<uint32_t*>(&h0), *reinterpret_cast<uint32_t*>(&h1));
        }
    }
    __syncthreads();

    // out-projection (ldmatrix + fp16 mma) + bias + residual + LayerNorm in registers
    int lr = lane >> 2, lc = lane & 3;
    uint32_t aoffb = ((uint32_t)(((lane & 15)) * AROWW + ((lane >> 4) << 2))) << 2;
    uint32_t boffb = ((uint32_t)(((((lane >> 4) & 1) << 3) + (lane & 7)) * AROWW
                                 + (((lane >> 3) & 1) << 2))) << 2;
    for (int strip = warp; strip < 10; strip += 8) {
        float acc[16][4];
#pragma unroll
        for (int nf = 0; nf < 16; nf++) {
            acc[nf][0] = 0.f; acc[nf][1] = 0.f; acc[nf][2] = 0.f; acc[nf][3] = 0.f;
        }
        uint32_t abase = ctx_u + (uint32_t)(strip * 16 * AROWW * 4) + aoffb;
#pragma unroll
        for (int ks = 0; ks < 8; ks++) {
            uint32_t af[4];
            ldsm4(af[0], af[1], af[2], af[3], abase + ks * 32);
#pragma unroll
            for (int p = 0; p < 8; p++) {
                uint32_t b0, b1, b2, b3;
                ldsm4(b0, b1, b2, b3, w_u + (uint32_t)(p * 16 * AROWW * 4) + boffb + ks * 32);
                mma_f16(acc[2 * p], af, b0, b1);
                mma_f16(acc[2 * p + 1], af, b2, b3);
            }
        }
        // residual + LN for the two rows owned by this thread
        int tr0 = strip * 16 + lr;
        int s0i = (S0 * 5 + tr0) / 5, tk0 = (S0 * 5 + tr0) % 5;
        int s1i = (S0 * 5 + tr0 + 8) / 5, tk1 = (S0 * 5 + tr0 + 8) % 5;
        const __half* x0 = g_xqkvh + (size_t)s0i * (NMOD * 512) + tk0 * 512;
        const __half* x1 = g_xqkvh + (size_t)s1i * (NMOD * 512) + tk1 * 512;
        float s0 = 0.f, q0 = 0.f, s1 = 0.f, q1 = 0.f;
#pragma unroll
        for (int nf = 0; nf < 16; nf++) {
            int col = nf * 8 + lc * 2;
            float2 ob = *reinterpret_cast<const float2*>(out_b + col);
            uint32_t xw0 = *reinterpret_cast<const uint32_t*>(x0 + col);
            uint32_t xw1 = *reinterpret_cast<const uint32_t*>(x1 + col);
            float2 xv0 = __half22float2(*reinterpret_cast<const __half2*>(&xw0));
            float2 xv1 = __half22float2(*reinterpret_cast<const __half2*>(&xw1));
            acc[nf][0] += ob.x + xv0.x;
            acc[nf][1] += ob.y + xv0.y;
            acc[nf][2] += ob.x + xv1.x;
            acc[nf][3] += ob.y + xv1.y;
            s0 += acc[nf][0] + acc[nf][1];
            q0 += acc[nf][0] * acc[nf][0] + acc[nf][1] * acc[nf][1];
            s1 += acc[nf][2] + acc[nf][3];
            q1 += acc[nf][2] * acc[nf][2] + acc[nf][3] * acc[nf][3];
        }
#pragma unroll
        for (int o = 1; o <= 2; o <<= 1) {
            s0 += __shfl_xor_sync(0xffffffffu, s0, o);
            q0 += __shfl_xor_sync(0xffffffffu, q0, o);
            s1 += __shfl_xor_sync(0xffffffffu, s1, o);
            q1 += __shfl_xor_sync(0xffffffffu, q1, o);
        }
        float mu0 = s0 * (1.f / 128.f);
        float rs0 = rsqrtf(q0 * (1.f / 128.f) - mu0 * mu0 + 1e-5f);
        float mu1 = s1 * (1.f / 128.f);
        float rs1 = rsqrtf(q1 * (1.f / 128.f) - mu1 * mu1 + 1e-5f);
        __half* y0 = g_yh + ((size_t)S0 * 5 + tr0) * 128;
        __half* y1 = g_yh + ((size_t)S0 * 5 + tr0 + 8) * 128;
#pragma unroll
        for (int nf = 0; nf < 16; nf++) {
            int col = nf * 8 + lc * 2;
            float2 gg = *reinterpret_cast<const float2*>(ln_g + col);
            float2 bb = *reinterpret_cast<const float2*>(ln_b + col);
            __half2 h0 = __floats2half2_rn((acc[nf][0] - mu0) * rs0 * gg.x + bb.x,
                                           (acc[nf][1] - mu0) * rs0 * gg.y + bb.y);
            __half2 h1 = __floats2half2_rn((acc[nf][2] - mu1) * rs1 * gg.x + bb.x,
                                           (acc[nf][3] - mu1) * rs1 * gg.y + bb.y);
            *reinterpret_cast<uint32_t*>(y0 + col) = *reinterpret_cast<uint32_t*>(&h0);
            *reinterpret_cast<uint32_t*>(y1 + col) = *reinterpret_cast<uint32_t*>(&h1);
        }
    }
}

// ---------------- launcher ----------------
extern "C" void kernel_launch(void* const* d_in, const int* in_sizes, int n_in,
                              void* d_out, int out_size) {
    const float* cat    = (const float*)d_in[0];
    const float* menu   = (const float*)d_in[1];
    const float* diner  = (const float*)d_in[2];
    const float* price  = (const float*)d_in[3];
    const float* review = (const float*)d_in[4];
    const float* Wc = (const float*)d_in[5];  const float* bc = (const float*)d_in[6];
    const float* Wm = (const float*)d_in[7];  const float* bm = (const float*)d_in[8];
    const float* Wd = (const float*)d_in[9];  const float* bd = (const float*)d_in[10];
    const float* Wp = (const float*)d_in[11]; const float* bp = (const float*)d_in[12];
    const float* Wr = (const float*)d_in[13]; const float* br = (const float*)d_in[14];
    const float* in_w = (const float*)d_in[15];  const float* in_b = (const float*)d_in[16];
    const float* out_w = (const float*)d_in[17]; const float* out_b = (const float*)d_in[18];
    const float* ln_g = (const float*)d_in[19];  const float* ln_b = (const float*)d_in[20];
    const float* fus_w = (const float*)d_in[21]; const float* fus_b = (const float*)d_in[22];

    int B = in_sizes[0] / 128;

    cudaFuncSetAttribute(gemmA_kernel, cudaFuncAttributeMaxDynamicSharedMemorySize, GEMM_SMEM);
    cudaFuncSetAttribute(gemmF_kernel, cudaFuncAttributeMaxDynamicSharedMemorySize, GEMM_SMEM);
    cudaFuncSetAttribute(attn_kernel, cudaFuncAttributeMaxDynamicSharedMemorySize, ATTN_SMEM);

    size_t off0 = 0;
    size_t off1 = off0 + (size_t)B * 128;
    size_t off2 = off1 + (size_t)B * 256;
    size_t off3 = off2 + (size_t)B * 64;
    size_t off4 = off3 + (size_t)B * 32;
    size_t off5 = off4 + (size_t)B * 512;   // fus_w

    // cvt: embeddings + fus_w -> fp16
    {
        CvtParams cp;
        cp.src[0] = cat;    cp.off[0] = off0; cp.n[0] = B * 128;
        cp.src[1] = menu;   cp.off[1] = off1; cp.n[1] = B * 256;
        cp.src[2] = diner;  cp.off[2] = off2; cp.n[2] = B * 64;
        cp.src[3] = price;  cp.off[3] = off3; cp.n[3] = B * 32;
        cp.src[4] = review; cp.off[4] = off4; cp.n[4] = B * 512;
        cp.src[5] = fus_w;  cp.off[5] = off5; cp.n[5] = 992 * 640;
        int maxn = B * 512;
        dim3 grid((maxn / 8 + 255) / 256, 6);
        cvt_kernel<<<grid, 256>>>(cp);
    }

    // prep: merged fp16 weights + fp32 biases
    {
        dim3 grid((512 * 512) / 256, 5);
        prep_all_kernel<<<grid, 256>>>(Wc, bc, Wm, bm, Wd, bd, Wp, bp, Wr, br,
                                       in_w, in_b);
    }

    // phase A: 5 modality GEMMs -> g_xqkvh (fp16)
    {
        GemmAParams p;
        p.aoff[0] = off0; p.K[0] = 128; p.woff[0] = 0;
        p.aoff[1] = off1; p.K[1] = 256; p.woff[1] = 512 * 128;
        p.aoff[2] = off2; p.K[2] = 64;  p.woff[2] = 512 * 384;
        p.aoff[3] = off3; p.K[3] = 32;  p.woff[3] = 512 * 448;
        p.aoff[4] = off4; p.K[4] = 512; p.woff[4] = 512 * 480;
        dim3 grid(4, B / 128, 5);
        gemmA_kernel<<<grid, 256, GEMM_SMEM>>>(p);
    }

    attn_kernel<<<B / 32, 256, ATTN_SMEM>>>(out_w, out_b, ln_g, ln_b);

    // fusion GEMM -> d_out
    {
        dim3 grid(8, B / 128);
        gemmF_kernel<<<grid, 256, GEMM_SMEM>>>(off5, fus_b, (float*)d_out);
    }
}

// round 10
// speedup vs baseline: 1.0006x; 1.0006x over previous
#include <cuda_runtime.h>
#include <cuda_fp16.h>
#include <cstdint>
#include <cstddef>

// ---------------- problem constants ----------------
#define NMOD 5
#define MAXB 65536

// ---------------- static scratch (device symbols) ----------------
__device__ __half g_xqkvh[(size_t)MAXB * NMOD * 512];          // [B][5][x|q|k|v] fp16
__device__ __half g_yh[(size_t)MAXB * 640];                    // post-LN (fp16)
__device__ __half g_eh[(size_t)MAXB * 992 + 640 * 992];        // fp16 embeddings + fus_w
__device__ __half g_W1h[512 * 992];                            // merged modality weights (fp16)
__device__ float  g_b1[NMOD * 512];                            // merged biases (fp32)

// ---------------- helpers ----------------
__device__ __forceinline__ void mma_f16(float c[4], const uint32_t a[4],
                                        uint32_t b0, uint32_t b1) {
    asm volatile(
        "mma.sync.aligned.m16n8k16.row.col.f32.f16.f16.f32 "
        "{%0,%1,%2,%3},{%4,%5,%6,%7},{%8,%9},{%0,%1,%2,%3};"
        : "+f"(c[0]), "+f"(c[1]), "+f"(c[2]), "+f"(c[3])
        : "r"(a[0]), "r"(a[1]), "r"(a[2]), "r"(a[3]), "r"(b0), "r"(b1));
}
__device__ __forceinline__ void ldsm4(uint32_t& r0, uint32_t& r1, uint32_t& r2,
                                      uint32_t& r3, uint32_t addr) {
    asm volatile("ldmatrix.sync.aligned.m8n8.x4.shared.b16 {%0,%1,%2,%3}, [%4];"
                 : "=r"(r0), "=r"(r1), "=r"(r2), "=r"(r3) : "r"(addr));
}
__device__ __forceinline__ uint32_t smem_u32(const void* p) {
    uint32_t a;
    asm("{ .reg .u64 t; cvta.to.shared.u64 t, %1; cvt.u32.u64 %0, t; }" : "=r"(a) : "l"(p));
    return a;
}
__device__ __forceinline__ void cp16(uint32_t dst, const void* src, bool v) {
    asm volatile("cp.async.cg.shared.global [%0], [%1], 16, %2;"
                 :: "r"(dst), "l"(src), "r"(v ? 16u : 0u));
}
#define CP_COMMIT() asm volatile("cp.async.commit_group;" ::: "memory")
#define CP_WAIT1()  asm volatile("cp.async.wait_group 1;" ::: "memory")
#define CP_WAIT0()  asm volatile("cp.async.wait_group 0;" ::: "memory")

// ---------------- cvt: fp32 -> fp16 for embeddings + fus_w ----------------
struct CvtParams {
    const float* src[6];
    size_t off[6];
    int n[6];
};
__global__ void cvt_kernel(CvtParams p) {
    int m = blockIdx.y;
    int idx = (blockIdx.x * 256 + threadIdx.x) * 8;
    if (idx >= p.n[m]) return;
    const float4* s = reinterpret_cast<const float4*>(p.src[m] + idx);
    float4 a = s[0], b = s[1];
    __half2 h0 = __floats2half2_rn(a.x, a.y);
    __half2 h1 = __floats2half2_rn(a.z, a.w);
    __half2 h2 = __floats2half2_rn(b.x, b.y);
    __half2 h3 = __floats2half2_rn(b.z, b.w);
    uint4 o;
    o.x = *reinterpret_cast<uint32_t*>(&h0);
    o.y = *reinterpret_cast<uint32_t*>(&h1);
    o.z = *reinterpret_cast<uint32_t*>(&h2);
    o.w = *reinterpret_cast<uint32_t*>(&h3);
    *reinterpret_cast<uint4*>(g_eh + p.off[m] + idx) = o;
}

// ---------------- prep: merged weights (fp16) + biases (fp32) ----------------
__global__ void prep_all_kernel(
    const float* __restrict__ Wc, const float* __restrict__ bc,
    const float* __restrict__ Wm, const float* __restrict__ bm,
    const float* __restrict__ Wd, const float* __restrict__ bd,
    const float* __restrict__ Wp, const float* __restrict__ bp,
    const float* __restrict__ Wr, const float* __restrict__ br,
    const float* __restrict__ in_w, const float* __restrict__ in_b) {
    int m = blockIdx.y;
    const float* Wmod; const float* bmod; int K; int off;
    switch (m) {
        case 0: Wmod = Wc; bmod = bc; K = 128; off = 0; break;
        case 1: Wmod = Wm; bmod = bm; K = 256; off = 512 * 128; break;
        case 2: Wmod = Wd; bmod = bd; K = 64;  off = 512 * 384; break;
        case 3: Wmod = Wp; bmod = bp; K = 32;  off = 512 * 448; break;
        default: Wmod = Wr; bmod = br; K = 512; off = 512 * 480; break;
    }
    int w = blockIdx.x * 256 + threadIdx.x;
    if (w >= 512 * K) return;
    int part = w & 3;
    int q = w >> 2;
    int K4 = K >> 2;
    int j = q / K4;
    int k4 = (q - j * K4) * 4;
    float4 acc = make_float4(0.f, 0.f, 0.f, 0.f);
    if (j < 128) {
        if (part == 0) acc = *reinterpret_cast<const float4*>(Wmod + (size_t)j * K + k4);
    } else {
        const float* iw = in_w + (size_t)(j - 128) * 128 + part * 32;
        const float* wp = Wmod + (size_t)(part * 32) * K + k4;
#pragma unroll 8
        for (int t = 0; t < 32; t++) {
            float wv = iw[t];
            float4 v = *reinterpret_cast<const float4*>(wp + (size_t)t * K);
            acc.x += wv * v.x; acc.y += wv * v.y; acc.z += wv * v.z; acc.w += wv * v.w;
        }
    }
#pragma unroll
    for (int d = 1; d <= 2; d <<= 1) {
        acc.x += __shfl_xor_sync(0xffffffffu, acc.x, d);
        acc.y += __shfl_xor_sync(0xffffffffu, acc.y, d);
        acc.z += __shfl_xor_sync(0xffffffffu, acc.z, d);
        acc.w += __shfl_xor_sync(0xffffffffu, acc.w, d);
    }
    if (part == 0) {
        __half2 h0 = __floats2half2_rn(acc.x, acc.y);
        __half2 h1 = __floats2half2_rn(acc.z, acc.w);
        *reinterpret_cast<uint2*>(g_W1h + off + (size_t)j * K + k4) =
            make_uint2(*reinterpret_cast<uint32_t*>(&h0), *reinterpret_cast<uint32_t*>(&h1));
        if (k4 == 0) {
            float bb;
            if (j < 128) bb = bmod[j];
            else {
                const float* iw2 = in_w + (size_t)(j - 128) * 128;
                float a = in_b[j - 128];
                for (int t = 0; t < 128; t++) a += iw2[t] * bmod[t];
                bb = a;
            }
            g_b1[m * 512 + j] = bb;
        }
    }
}

// ---------------- fp16 cp.async GEMM core (ldmatrix frags, 1 barrier/ktile) ----------------
#define BK 64
#define ROWH 72
#define ROWWD 36
#define STAGE_H (256 * ROWH)
#define STAGE_B (STAGE_H * 2)
#define NSTAGE 3
#define GEMM_SMEM (NSTAGE * STAGE_B)     // 110592 bytes

__device__ __forceinline__ void gemm_core(
    const __half* __restrict__ Ablk, int lda,
    const __half* __restrict__ W, int ldw,
    const float* __restrict__ bias,
    float* outf, __half* outh, int ldo,
    int N, int K, int Mbase, int nbase,
    uint32_t shu) {

    int tid = threadIdx.x, warp = tid >> 5, lane = tid & 31;
    int wm = warp >> 2, wn = warp & 3;
    int nkt = (K + BK - 1) / BK;

    float acc[4][4][4];
#pragma unroll
    for (int i = 0; i < 4; i++)
#pragma unroll
        for (int j = 0; j < 4; j++)
#pragma unroll
            for (int q = 0; q < 4; q++) acc[i][j][q] = 0.f;

    auto load_stage = [&](int kt, int st) {
        int k0 = kt * BK;
        uint32_t dbase = shu + st * STAGE_B;
#pragma unroll
        for (int i = 0; i < 8; i++) {
            int c = tid + (i << 8);
            int row = c >> 3, seg = c & 7;
            int kk = k0 + seg * 8;
            const __half* src;
            bool v;
            if (row < 128) {
                v = kk < K;
                src = v ? (Ablk + (size_t)row * lda + kk) : Ablk;
            } else {
                int n = row - 128;
                v = (nbase + n < N) && (kk < K);
                src = v ? (W + (size_t)(nbase + n) * ldw + kk) : W;
            }
            cp16(dbase + (uint32_t)(row * ROWH + seg * 8) * 2, src, v);
        }
        CP_COMMIT();
    };

    load_stage(0, 0);
    if (nkt > 1) load_stage(1, 1);

    // per-lane ldmatrix byte offsets within a stage
    uint32_t aoffb = ((uint32_t)((wm * 64 + (lane & 15)) * ROWWD + ((lane >> 4) << 2))) << 2;
    uint32_t boffb = ((uint32_t)((128 + wn * 32 + (((lane >> 4) & 1) << 3) + (lane & 7)) * ROWWD
                                 + (((lane >> 3) & 1) << 2))) << 2;

    for (int kt = 0; kt < nkt; kt++) {
        int st = kt % 3;
        // stage kt is the (kt+1)-th committed group; groups committed so far = min(nkt, kt+2)
        if (kt + 1 < nkt) { CP_WAIT1(); } else { CP_WAIT0(); }
        __syncthreads();                       // single barrier per ktile: orders WAR + visibility
        if (kt + 2 < nkt) load_stage(kt + 2, (kt + 2) % 3);

        uint32_t sb = shu + st * STAGE_B;
#pragma unroll
        for (int ks = 0; ks < 4; ks++) {
            uint32_t kb = sb + ks * 32;
            uint32_t af[4][4];
#pragma unroll
            for (int mf = 0; mf < 4; mf++)
                ldsm4(af[mf][0], af[mf][1], af[mf][2], af[mf][3],
                      kb + aoffb + mf * (16 * ROWWD * 4));
            uint32_t p0[4], p1[4];
            ldsm4(p0[0], p0[1], p0[2], p0[3], kb + boffb);
            ldsm4(p1[0], p1[1], p1[2], p1[3], kb + boffb + 16 * ROWWD * 4);
#pragma unroll
            for (int mf = 0; mf < 4; mf++) {
                mma_f16(acc[mf][0], af[mf], p0[0], p0[1]);
                mma_f16(acc[mf][1], af[mf], p0[2], p0[3]);
                mma_f16(acc[mf][2], af[mf], p1[0], p1[1]);
                mma_f16(acc[mf][3], af[mf], p1[2], p1[3]);
            }
        }
    }

    int lr = lane >> 2, lc = lane & 3;
    if (outh) {
#pragma unroll
        for (int mf = 0; mf < 4; mf++) {
            int row0 = Mbase + wm * 64 + mf * 16 + lr;
#pragma unroll
            for (int nf = 0; nf < 4; nf++) {
                int col = nbase + wn * 32 + nf * 8 + lc * 2;
                if (col < N) {
                    float2 bv = *reinterpret_cast<const float2*>(bias + col);
                    __half2 h0 = __floats2half2_rn(acc[mf][nf][0] + bv.x, acc[mf][nf][1] + bv.y);
                    __half2 h1 = __floats2half2_rn(acc[mf][nf][2] + bv.x, acc[mf][nf][3] + bv.y);
                    *reinterpret_cast<uint32_t*>(outh + (size_t)row0 * ldo + col) =
                        *reinterpret_cast<uint32_t*>(&h0);
                    *reinterpret_cast<uint32_t*>(outh + (size_t)(row0 + 8) * ldo + col) =
                        *reinterpret_cast<uint32_t*>(&h1);
                }
            }
        }
    } else {
#pragma unroll
        for (int mf = 0; mf < 4; mf++) {
            int row0 = Mbase + wm * 64 + mf * 16 + lr;
#pragma unroll
            for (int nf = 0; nf < 4; nf++) {
                int col = nbase + wn * 32 + nf * 8 + lc * 2;
                if (col < N) {
                    float2 bv = *reinterpret_cast<const float2*>(bias + col);
                    float2 v0 = make_float2(acc[mf][nf][0] + bv.x, acc[mf][nf][1] + bv.y);
                    float2 v1 = make_float2(acc[mf][nf][2] + bv.x, acc[mf][nf][3] + bv.y);
                    *reinterpret_cast<float2*>(outf + (size_t)row0 * ldo + col) = v0;
                    *reinterpret_cast<float2*>(outf + (size_t)(row0 + 8) * ldo + col) = v1;
                }
            }
        }
    }
}

struct GemmAParams {
    size_t aoff[5];
    int K[5];
    int woff[5];
};

// grid: (x = N-tile(4), y = M-tile, z = modality); output fp16 into g_xqkvh
__global__ void __launch_bounds__(256, 2) gemmA_kernel(GemmAParams p) {
    extern __shared__ __half sh[];
    int m = blockIdx.z;
    int Mbase = blockIdx.y * 128, nbase = blockIdx.x * 128;
    gemm_core(g_eh + p.aoff[m] + (size_t)Mbase * p.K[m], p.K[m],
              g_W1h + p.woff[m], p.K[m], g_b1 + m * 512,
              nullptr, g_xqkvh + m * 512, NMOD * 512, 512, p.K[m],
              Mbase, nbase, smem_u32(sh));
}

// grid: (x = N-tile(8), y = M-tile)
__global__ void __launch_bounds__(256, 2) gemmF_kernel(
    size_t fw_off, const float* __restrict__ fus_b, float* __restrict__ out) {
    extern __shared__ __half sh[];
    int Mbase = blockIdx.y * 128, nbase = blockIdx.x * 128;
    gemm_core(g_yh + (size_t)Mbase * 640, 640,
              g_eh + fw_off, 640, fus_b,
              out, nullptr, 992, 992, 640, Mbase, nbase, smem_u32(sh));
}

// ---------------- fused attention + out-proj + residual + LayerNorm ----------------
#define AROWW 68                                  // words per smem row (136 halves)
#define ATTN_SMEM ((160 + 128) * AROWW * 4)       // 78336 bytes

__global__ void __launch_bounds__(256, 2) attn_kernel(
    const float* __restrict__ out_w, const float* __restrict__ out_b,
    const float* __restrict__ ln_g, const float* __restrict__ ln_b) {
    extern __shared__ uint32_t smw[];
    uint32_t* s_ctx = smw;                 // [160][AROWW] words (fp16 ctx)
    uint32_t* s_w = smw + 160 * AROWW;     // [128][AROWW] words (fp16 out_w)

    int tid = threadIdx.x, warp = tid >> 5, lane = tid & 31;
    int S0 = blockIdx.x * 32;
    uint32_t ctx_u = smem_u32(s_ctx);
    uint32_t w_u = smem_u32(s_w);

    // stage out_w -> fp16 smem
    for (int idx = tid; idx < 128 * 16; idx += 256) {
        int r = idx >> 4;
        int c8 = (idx & 15) * 8;
        const float4* p = reinterpret_cast<const float4*>(out_w + (size_t)r * 128 + c8);
        float4 a = p[0], b = p[1];
        __half2 h0 = __floats2half2_rn(a.x, a.y);
        __half2 h1 = __floats2half2_rn(a.z, a.w);
        __half2 h2 = __floats2half2_rn(b.x, b.y);
        __half2 h3 = __floats2half2_rn(b.z, b.w);
        uint4 o;
        o.x = *reinterpret_cast<uint32_t*>(&h0);
        o.y = *reinterpret_cast<uint32_t*>(&h1);
        o.z = *reinterpret_cast<uint32_t*>(&h2);
        o.w = *reinterpret_cast<uint32_t*>(&h3);
        *reinterpret_cast<uint4*>(s_w + r * AROWW + (c8 >> 1)) = o;
    }

    // softmax + ctx (fp16 inputs, fp32 math), 4 samples per warp
#pragma unroll
    for (int t = 0; t < 4; t++) {
        int sl = warp * 4 + t;
        int s = S0 + sl;
        const __half* rb = g_xqkvh + (size_t)s * (NMOD * 512);
        float attn[5] = {0.f, 0.f, 0.f, 0.f, 0.f};
        if (lane < 20) {
            int h = lane / 5, i = lane % 5;
            float qv[32];
            {
                const uint4* qp = reinterpret_cast<const uint4*>(rb + i * 512 + 128 + h * 32);
#pragma unroll
                for (int u = 0; u < 4; u++) {
                    uint4 w = qp[u];
                    const uint32_t ww[4] = {w.x, w.y, w.z, w.w};
#pragma unroll
                    for (int e = 0; e < 4; e++) {
                        float2 f = __half22float2(*reinterpret_cast<const __half2*>(&ww[e]));
                        qv[u * 8 + e * 2] = f.x; qv[u * 8 + e * 2 + 1] = f.y;
                    }
                }
            }
            float sc[5];
#pragma unroll
            for (int j = 0; j < 5; j++) {
                const uint4* kp = reinterpret_cast<const uint4*>(rb + j * 512 + 256 + h * 32);
                float a = 0.f;
#pragma unroll
                for (int u = 0; u < 4; u++) {
                    uint4 w = kp[u];
                    const uint32_t ww[4] = {w.x, w.y, w.z, w.w};
#pragma unroll
                    for (int e = 0; e < 4; e++) {
                        float2 f = __half22float2(*reinterpret_cast<const __half2*>(&ww[e]));
                        a += qv[u * 8 + e * 2] * f.x + qv[u * 8 + e * 2 + 1] * f.y;
                    }
                }
                sc[j] = a * 0.17677669529663687f;   // 1/sqrt(32)
            }
            float mx = sc[0];
#pragma unroll
            for (int j = 1; j < 5; j++) mx = fmaxf(mx, sc[j]);
            float den = 0.f;
#pragma unroll
            for (int j = 0; j < 5; j++) { attn[j] = __expf(sc[j] - mx); den += attn[j]; }
            float inv = 1.f / den;
#pragma unroll
            for (int j = 0; j < 5; j++) attn[j] *= inv;
        }
        __syncwarp();
        int h2 = lane >> 3;
#pragma unroll
        for (int i = 0; i < 5; i++) {
            float a0 = 0.f, a1 = 0.f, a2 = 0.f, a3 = 0.f;
#pragma unroll
            for (int j = 0; j < 5; j++) {
                float a = __shfl_sync(0xffffffffu, attn[j], h2 * 5 + i);
                uint2 w = *reinterpret_cast<const uint2*>(rb + j * 512 + 384 + lane * 4);
                float2 f0 = __half22float2(*reinterpret_cast<const __half2*>(&w.x));
                float2 f1 = __half22float2(*reinterpret_cast<const __half2*>(&w.y));
                a0 += a * f0.x; a1 += a * f0.y; a2 += a * f1.x; a3 += a * f1.y;
            }
            __half2 h0 = __floats2half2_rn(a0, a1);
            __half2 h1 = __floats2half2_rn(a2, a3);
            *reinterpret_cast<uint2*>(s_ctx + (sl * 5 + i) * AROWW + lane * 2) =
                make_uint2(*reinterpret_cast<uint32_t*>(&h0), *reinterpret_cast<uint32_t*>(&h1));
        }
    }
    __syncthreads();

    // out-projection (ldmatrix + fp16 mma) + bias + residual + LayerNorm in registers
    int lr = lane >> 2, lc = lane & 3;
    uint32_t aoffb = ((uint32_t)(((lane & 15)) * AROWW + ((lane >> 4) << 2))) << 2;
    uint32_t boffb = ((uint32_t)(((((lane >> 4) & 1) << 3) + (lane & 7)) * AROWW
                                 + (((lane >> 3) & 1) << 2))) << 2;
    for (int strip = warp; strip < 10; strip += 8) {
        float acc[16][4];
#pragma unroll
        for (int nf = 0; nf < 16; nf++) {
            acc[nf][0] = 0.f; acc[nf][1] = 0.f; acc[nf][2] = 0.f; acc[nf][3] = 0.f;
        }
        uint32_t abase = ctx_u + (uint32_t)(strip * 16 * AROWW * 4) + aoffb;
#pragma unroll
        for (int ks = 0; ks < 8; ks++) {
            uint32_t af[4];
            ldsm4(af[0], af[1], af[2], af[3], abase + ks * 32);
#pragma unroll
            for (int p = 0; p < 8; p++) {
                uint32_t b0, b1, b2, b3;
                ldsm4(b0, b1, b2, b3, w_u + (uint32_t)(p * 16 * AROWW * 4) + boffb + ks * 32);
                mma_f16(acc[2 * p], af, b0, b1);
                mma_f16(acc[2 * p + 1], af, b2, b3);
            }
        }
        // residual + LN for the two rows owned by this thread
        int tr0 = strip * 16 + lr;
        int s0i = (S0 * 5 + tr0) / 5, tk0 = (S0 * 5 + tr0) % 5;
        int s1i = (S0 * 5 + tr0 + 8) / 5, tk1 = (S0 * 5 + tr0 + 8) % 5;
        const __half* x0 = g_xqkvh + (size_t)s0i * (NMOD * 512) + tk0 * 512;
        const __half* x1 = g_xqkvh + (size_t)s1i * (NMOD * 512) + tk1 * 512;
        float s0 = 0.f, q0 = 0.f, s1 = 0.f, q1 = 0.f;
#pragma unroll
        for (int nf = 0; nf < 16; nf++) {
            int col = nf * 8 + lc * 2;
            float2 ob = *reinterpret_cast<const float2*>(out_b + col);
            uint32_t xw0 = *reinterpret_cast<const uint32_t*>(x0 + col);
            uint32_t xw1 = *reinterpret_cast<const uint32_t*>(x1 + col);
            float2 xv0 = __half22float2(*reinterpret_cast<const __half2*>(&xw0));
            float2 xv1 = __half22float2(*reinterpret_cast<const __half2*>(&xw1));
            acc[nf][0] += ob.x + xv0.x;
            acc[nf][1] += ob.y + xv0.y;
            acc[nf][2] += ob.x + xv1.x;
            acc[nf][3] += ob.y + xv1.y;
            s0 += acc[nf][0] + acc[nf][1];
            q0 += acc[nf][0] * acc[nf][0] + acc[nf][1] * acc[nf][1];
            s1 += acc[nf][2] + acc[nf][3];
            q1 += acc[nf][2] * acc[nf][2] + acc[nf][3] * acc[nf][3];
        }
#pragma unroll
        for (int o = 1; o <= 2; o <<= 1) {
            s0 += __shfl_xor_sync(0xffffffffu, s0, o);
            q0 += __shfl_xor_sync(0xffffffffu, q0, o);
            s1 += __shfl_xor_sync(0xffffffffu, s1, o);
            q1 += __shfl_xor_sync(0xffffffffu, q1, o);
        }
        float mu0 = s0 * (1.f / 128.f);
        float rs0 = rsqrtf(q0 * (1.f / 128.f) - mu0 * mu0 + 1e-5f);
        float mu1 = s1 * (1.f / 128.f);
        float rs1 = rsqrtf(q1 * (1.f / 128.f) - mu1 * mu1 + 1e-5f);
        __half* y0 = g_yh + ((size_t)S0 * 5 + tr0) * 128;
        __half* y1 = g_yh + ((size_t)S0 * 5 + tr0 + 8) * 128;
#pragma unroll
        for (int nf = 0; nf < 16; nf++) {
            int col = nf * 8 + lc * 2;
            float2 gg = *reinterpret_cast<const float2*>(ln_g + col);
            float2 bb = *reinterpret_cast<const float2*>(ln_b + col);
            __half2 h0 = __floats2half2_rn((acc[nf][0] - mu0) * rs0 * gg.x + bb.x,
                                           (acc[nf][1] - mu0) * rs0 * gg.y + bb.y);
            __half2 h1 = __floats2half2_rn((acc[nf][2] - mu1) * rs1 * gg.x + bb.x,
                                           (acc[nf][3] - mu1) * rs1 * gg.y + bb.y);
            *reinterpret_cast<uint32_t*>(y0 + col) = *reinterpret_cast<uint32_t*>(&h0);
            *reinterpret_cast<uint32_t*>(y1 + col) = *reinterpret_cast<uint32_t*>(&h1);
        }
    }
}

// ---------------- launcher ----------------
extern "C" void kernel_launch(void* const* d_in, const int* in_sizes, int n_in,
                              void* d_out, int out_size) {
    const float* cat    = (const float*)d_in[0];
    const float* menu   = (const float*)d_in[1];
    const float* diner  = (const float*)d_in[2];
    const float* price  = (const float*)d_in[3];
    const float* review = (const float*)d_in[4];
    const float* Wc = (const float*)d_in[5];  const float* bc = (const float*)d_in[6];
    const float* Wm = (const float*)d_in[7];  const float* bm = (const float*)d_in[8];
    const float* Wd = (const float*)d_in[9];  const float* bd = (const float*)d_in[10];
    const float* Wp = (const float*)d_in[11]; const float* bp = (const float*)d_in[12];
    const float* Wr = (const float*)d_in[13]; const float* br = (const float*)d_in[14];
    const float* in_w = (const float*)d_in[15];  const float* in_b = (const float*)d_in[16];
    const float* out_w = (const float*)d_in[17]; const float* out_b = (const float*)d_in[18];
    const float* ln_g = (const float*)d_in[19];  const float* ln_b = (const float*)d_in[20];
    const float* fus_w = (const float*)d_in[21]; const float* fus_b = (const float*)d_in[22];

    int B = in_sizes[0] / 128;

    cudaFuncSetAttribute(gemmA_kernel, cudaFuncAttributeMaxDynamicSharedMemorySize, GEMM_SMEM);
    cudaFuncSetAttribute(gemmF_kernel, cudaFuncAttributeMaxDynamicSharedMemorySize, GEMM_SMEM);
    cudaFuncSetAttribute(attn_kernel, cudaFuncAttributeMaxDynamicSharedMemorySize, ATTN_SMEM);

    size_t off0 = 0;
    size_t off1 = off0 + (size_t)B * 128;
    size_t off2 = off1 + (size_t)B * 256;
    size_t off3 = off2 + (size_t)B * 64;
    size_t off4 = off3 + (size_t)B * 32;
    size_t off5 = off4 + (size_t)B * 512;   // fus_w

    // cvt: embeddings + fus_w -> fp16
    {
        CvtParams cp;
        cp.src[0] = cat;    cp.off[0] = off0; cp.n[0] = B * 128;
        cp.src[1] = menu;   cp.off[1] = off1; cp.n[1] = B * 256;
        cp.src[2] = diner;  cp.off[2] = off2; cp.n[2] = B * 64;
        cp.src[3] = price;  cp.off[3] = off3; cp.n[3] = B * 32;
        cp.src[4] = review; cp.off[4] = off4; cp.n[4] = B * 512;
        cp.src[5] = fus_w;  cp.off[5] = off5; cp.n[5] = 992 * 640;
        int maxn = B * 512;
        dim3 grid((maxn / 8 + 255) / 256, 6);
        cvt_kernel<<<grid, 256>>>(cp);
    }

    // prep: merged fp16 weights + fp32 biases
    {
        dim3 grid((512 * 512) / 256, 5);
        prep_all_kernel<<<grid, 256>>>(Wc, bc, Wm, bm, Wd, bd, Wp, bp, Wr, br,
                                       in_w, in_b);
    }

    // phase A: 5 modality GEMMs -> g_xqkvh (fp16)
    {
        GemmAParams p;
        p.aoff[0] = off0; p.K[0] = 128; p.woff[0] = 0;
        p.aoff[1] = off1; p.K[1] = 256; p.woff[1] = 512 * 128;
        p.aoff[2] = off2; p.K[2] = 64;  p.woff[2] = 512 * 384;
        p.aoff[3] = off3; p.K[3] = 32;  p.woff[3] = 512 * 448;
        p.aoff[4] = off4; p.K[4] = 512; p.woff[4] = 512 * 480;
        dim3 grid(4, B / 128, 5);
        gemmA_kernel<<<grid, 256, GEMM_SMEM>>>(p);
    }

    attn_kernel<<<B / 32, 256, ATTN_SMEM>>>(out_w, out_b, ln_g, ln_b);

    // fusion GEMM -> d_out
    {
        dim3 grid(8, B / 128);
        gemmF_kernel<<<grid, 256, GEMM_SMEM>>>(off5, fus_b, (float*)d_out);
    }
}

// round 11
// speedup vs baseline: 1.0036x; 1.0030x over previous
#include <cuda_runtime.h>
#include <cuda_fp16.h>
#include <cstdint>
#include <cstddef>

// ---------------- problem constants ----------------
#define NMOD 5
#define MAXB 65536

// ---------------- static scratch (device symbols) ----------------
__device__ __half g_xqkvh[(size_t)MAXB * NMOD * 512];          // [B][5][x|q|k|v] fp16
__device__ __half g_yh[(size_t)MAXB * 640];                    // post-LN (fp16)
__device__ __half g_eh[(size_t)MAXB * 992 + 640 * 992];        // fp16 embeddings + fus_w
__device__ __half g_W1h[512 * 992];                            // merged modality weights (fp16)
__device__ float  g_b1[NMOD * 512];                            // merged biases (fp32)

// ---------------- helpers ----------------
__device__ __forceinline__ void mma_f16(float c[4], const uint32_t a[4],
                                        uint32_t b0, uint32_t b1) {
    asm volatile(
        "mma.sync.aligned.m16n8k16.row.col.f32.f16.f16.f32 "
        "{%0,%1,%2,%3},{%4,%5,%6,%7},{%8,%9},{%0,%1,%2,%3};"
        : "+f"(c[0]), "+f"(c[1]), "+f"(c[2]), "+f"(c[3])
        : "r"(a[0]), "r"(a[1]), "r"(a[2]), "r"(a[3]), "r"(b0), "r"(b1));
}
__device__ __forceinline__ void ldsm4(uint32_t& r0, uint32_t& r1, uint32_t& r2,
                                      uint32_t& r3, uint32_t addr) {
    asm volatile("ldmatrix.sync.aligned.m8n8.x4.shared.b16 {%0,%1,%2,%3}, [%4];"
                 : "=r"(r0), "=r"(r1), "=r"(r2), "=r"(r3) : "r"(addr));
}
__device__ __forceinline__ uint32_t smem_u32(const void* p) {
    uint32_t a;
    asm("{ .reg .u64 t; cvta.to.shared.u64 t, %1; cvt.u32.u64 %0, t; }" : "=r"(a) : "l"(p));
    return a;
}
__device__ __forceinline__ void cp16(uint32_t dst, const void* src, bool v) {
    asm volatile("cp.async.cg.shared.global [%0], [%1], 16, %2;"
                 :: "r"(dst), "l"(src), "r"(v ? 16u : 0u));
}
#define CP_COMMIT() asm volatile("cp.async.commit_group;" ::: "memory")
#define CP_WAIT1()  asm volatile("cp.async.wait_group 1;" ::: "memory")
#define CP_WAIT0()  asm volatile("cp.async.wait_group 0;" ::: "memory")

// ---------------- cvt: fp32 -> fp16 for embeddings + fus_w ----------------
struct CvtParams {
    const float* src[6];
    size_t off[6];
    int n[6];
};
__global__ void cvt_kernel(CvtParams p) {
    int m = blockIdx.y;
    int idx = (blockIdx.x * 256 + threadIdx.x) * 8;
    if (idx >= p.n[m]) return;
    const float4* s = reinterpret_cast<const float4*>(p.src[m] + idx);
    float4 a = s[0], b = s[1];
    __half2 h0 = __floats2half2_rn(a.x, a.y);
    __half2 h1 = __floats2half2_rn(a.z, a.w);
    __half2 h2 = __floats2half2_rn(b.x, b.y);
    __half2 h3 = __floats2half2_rn(b.z, b.w);
    uint4 o;
    o.x = *reinterpret_cast<uint32_t*>(&h0);
    o.y = *reinterpret_cast<uint32_t*>(&h1);
    o.z = *reinterpret_cast<uint32_t*>(&h2);
    o.w = *reinterpret_cast<uint32_t*>(&h3);
    *reinterpret_cast<uint4*>(g_eh + p.off[m] + idx) = o;
}

// ---------------- prep: merged weights (fp16) + biases (fp32) ----------------
__global__ void prep_all_kernel(
    const float* __restrict__ Wc, const float* __restrict__ bc,
    const float* __restrict__ Wm, const float* __restrict__ bm,
    const float* __restrict__ Wd, const float* __restrict__ bd,
    const float* __restrict__ Wp, const float* __restrict__ bp,
    const float* __restrict__ Wr, const float* __restrict__ br,
    const float* __restrict__ in_w, const float* __restrict__ in_b) {
    int m = blockIdx.y;
    const float* Wmod; const float* bmod; int K; int off;
    switch (m) {
        case 0: Wmod = Wc; bmod = bc; K = 128; off = 0; break;
        case 1: Wmod = Wm; bmod = bm; K = 256; off = 512 * 128; break;
        case 2: Wmod = Wd; bmod = bd; K = 64;  off = 512 * 384; break;
        case 3: Wmod = Wp; bmod = bp; K = 32;  off = 512 * 448; break;
        default: Wmod = Wr; bmod = br; K = 512; off = 512 * 480; break;
    }
    int w = blockIdx.x * 256 + threadIdx.x;
    if (w >= 512 * K) return;
    int part = w & 3;
    int q = w >> 2;
    int K4 = K >> 2;
    int j = q / K4;
    int k4 = (q - j * K4) * 4;
    float4 acc = make_float4(0.f, 0.f, 0.f, 0.f);
    if (j < 128) {
        if (part == 0) acc = *reinterpret_cast<const float4*>(Wmod + (size_t)j * K + k4);
    } else {
        const float* iw = in_w + (size_t)(j - 128) * 128 + part * 32;
        const float* wp = Wmod + (size_t)(part * 32) * K + k4;
#pragma unroll 8
        for (int t = 0; t < 32; t++) {
            float wv = iw[t];
            float4 v = *reinterpret_cast<const float4*>(wp + (size_t)t * K);
            acc.x += wv * v.x; acc.y += wv * v.y; acc.z += wv * v.z; acc.w += wv * v.w;
        }
    }
#pragma unroll
    for (int d = 1; d <= 2; d <<= 1) {
        acc.x += __shfl_xor_sync(0xffffffffu, acc.x, d);
        acc.y += __shfl_xor_sync(0xffffffffu, acc.y, d);
        acc.z += __shfl_xor_sync(0xffffffffu, acc.z, d);
        acc.w += __shfl_xor_sync(0xffffffffu, acc.w, d);
    }
    if (part == 0) {
        __half2 h0 = __floats2half2_rn(acc.x, acc.y);
        __half2 h1 = __floats2half2_rn(acc.z, acc.w);
        *reinterpret_cast<uint2*>(g_W1h + off + (size_t)j * K + k4) =
            make_uint2(*reinterpret_cast<uint32_t*>(&h0), *reinterpret_cast<uint32_t*>(&h1));
        if (k4 == 0) {
            float bb;
            if (j < 128) bb = bmod[j];
            else {
                const float* iw2 = in_w + (size_t)(j - 128) * 128;
                float a = in_b[j - 128];
                for (int t = 0; t < 128; t++) a += iw2[t] * bmod[t];
                bb = a;
            }
            g_b1[m * 512 + j] = bb;
        }
    }
}

// ---------------- fp16 cp.async GEMM core (ldmatrix frags, 1 barrier/ktile) ----------------
#define BK 64
#define ROWH 72
#define ROWWD 36
#define STAGE_H (256 * ROWH)
#define STAGE_B (STAGE_H * 2)
#define NSTAGE 3
#define GEMM_SMEM (NSTAGE * STAGE_B)     // 110592 bytes

__device__ __forceinline__ void gemm_core(
    const __half* __restrict__ Ablk, int lda,
    const __half* __restrict__ W, int ldw,
    const float* __restrict__ bias,
    float* outf, __half* outh, int ldo,
    int N, int K, int Mbase, int nbase,
    uint32_t shu) {

    int tid = threadIdx.x, warp = tid >> 5, lane = tid & 31;
    int wm = warp >> 2, wn = warp & 3;
    int nkt = (K + BK - 1) / BK;

    float acc[4][4][4];
#pragma unroll
    for (int i = 0; i < 4; i++)
#pragma unroll
        for (int j = 0; j < 4; j++)
#pragma unroll
            for (int q = 0; q < 4; q++) acc[i][j][q] = 0.f;

    auto load_stage = [&](int kt, int st) {
        int k0 = kt * BK;
        uint32_t dbase = shu + st * STAGE_B;
#pragma unroll
        for (int i = 0; i < 8; i++) {
            int c = tid + (i << 8);
            int row = c >> 3, seg = c & 7;
            int kk = k0 + seg * 8;
            const __half* src;
            bool v;
            if (row < 128) {
                v = kk < K;
                src = v ? (Ablk + (size_t)row * lda + kk) : Ablk;
            } else {
                int n = row - 128;
                v = (nbase + n < N) && (kk < K);
                src = v ? (W + (size_t)(nbase + n) * ldw + kk) : W;
            }
            cp16(dbase + (uint32_t)(row * ROWH + seg * 8) * 2, src, v);
        }
        CP_COMMIT();
    };

    load_stage(0, 0);
    if (nkt > 1) load_stage(1, 1);

    // per-lane ldmatrix byte offsets within a stage
    uint32_t aoffb = ((uint32_t)((wm * 64 + (lane & 15)) * ROWWD + ((lane >> 4) << 2))) << 2;
    uint32_t boffb = ((uint32_t)((128 + wn * 32 + (((lane >> 4) & 1) << 3) + (lane & 7)) * ROWWD
                                 + (((lane >> 3) & 1) << 2))) << 2;

    for (int kt = 0; kt < nkt; kt++) {
        int st = kt % 3;
        // stage kt is the (kt+1)-th committed group; groups committed so far = min(nkt, kt+2)
        if (kt + 1 < nkt) { CP_WAIT1(); } else { CP_WAIT0(); }
        __syncthreads();                       // single barrier per ktile: orders WAR + visibility
        if (kt + 2 < nkt) load_stage(kt + 2, (kt + 2) % 3);

        uint32_t sb = shu + st * STAGE_B;
#pragma unroll
        for (int ks = 0; ks < 4; ks++) {
            uint32_t kb = sb + ks * 32;
            uint32_t af[4][4];
#pragma unroll
            for (int mf = 0; mf < 4; mf++)
                ldsm4(af[mf][0], af[mf][1], af[mf][2], af[mf][3],
                      kb + aoffb + mf * (16 * ROWWD * 4));
            uint32_t p0[4], p1[4];
            ldsm4(p0[0], p0[1], p0[2], p0[3], kb + boffb);
            ldsm4(p1[0], p1[1], p1[2], p1[3], kb + boffb + 16 * ROWWD * 4);
#pragma unroll
            for (int mf = 0; mf < 4; mf++) {
                mma_f16(acc[mf][0], af[mf], p0[0], p0[1]);
                mma_f16(acc[mf][1], af[mf], p0[2], p0[3]);
                mma_f16(acc[mf][2], af[mf], p1[0], p1[1]);
                mma_f16(acc[mf][3], af[mf], p1[2], p1[3]);
            }
        }
    }

    int lr = lane >> 2, lc = lane & 3;
    if (outh) {
#pragma unroll
        for (int mf = 0; mf < 4; mf++) {
            int row0 = Mbase + wm * 64 + mf * 16 + lr;
#pragma unroll
            for (int nf = 0; nf < 4; nf++) {
                int col = nbase + wn * 32 + nf * 8 + lc * 2;
                if (col < N) {
                    float2 bv = *reinterpret_cast<const float2*>(bias + col);
                    __half2 h0 = __floats2half2_rn(acc[mf][nf][0] + bv.x, acc[mf][nf][1] + bv.y);
                    __half2 h1 = __floats2half2_rn(acc[mf][nf][2] + bv.x, acc[mf][nf][3] + bv.y);
                    *reinterpret_cast<uint32_t*>(outh + (size_t)row0 * ldo + col) =
                        *reinterpret_cast<uint32_t*>(&h0);
                    *reinterpret_cast<uint32_t*>(outh + (size_t)(row0 + 8) * ldo + col) =
                        *reinterpret_cast<uint32_t*>(&h1);
                }
            }
        }
    } else {
#pragma unroll
        for (int mf = 0; mf < 4; mf++) {
            int row0 = Mbase + wm * 64 + mf * 16 + lr;
#pragma unroll
            for (int nf = 0; nf < 4; nf++) {
                int col = nbase + wn * 32 + nf * 8 + lc * 2;
                if (col < N) {
                    float2 bv = *reinterpret_cast<const float2*>(bias + col);
                    float2 v0 = make_float2(acc[mf][nf][0] + bv.x, acc[mf][nf][1] + bv.y);
                    float2 v1 = make_float2(acc[mf][nf][2] + bv.x, acc[mf][nf][3] + bv.y);
                    *reinterpret_cast<float2*>(outf + (size_t)row0 * ldo + col) = v0;
                    *reinterpret_cast<float2*>(outf + (size_t)(row0 + 8) * ldo + col) = v1;
                }
            }
        }
    }
}

struct GemmAParams {
    size_t aoff[5];
    int K[5];
    int woff[5];
};

// grid: (x = N-tile(4), y = M-tile, z = modality); output fp16 into g_xqkvh
__global__ void __launch_bounds__(256, 2) gemmA_kernel(GemmAParams p) {
    extern __shared__ __half sh[];
    int m = blockIdx.z;
    int Mbase = blockIdx.y * 128, nbase = blockIdx.x * 128;
    gemm_core(g_eh + p.aoff[m] + (size_t)Mbase * p.K[m], p.K[m],
              g_W1h + p.woff[m], p.K[m], g_b1 + m * 512,
              nullptr, g_xqkvh + m * 512, NMOD * 512, 512, p.K[m],
              Mbase, nbase, smem_u32(sh));
}

// grid: (x = N-tile(8), y = M-tile)
__global__ void __launch_bounds__(256, 2) gemmF_kernel(
    size_t fw_off, const float* __restrict__ fus_b, float* __restrict__ out) {
    extern __shared__ __half sh[];
    int Mbase = blockIdx.y * 128, nbase = blockIdx.x * 128;
    gemm_core(g_yh + (size_t)Mbase * 640, 640,
              g_eh + fw_off, 640, fus_b,
              out, nullptr, 992, 992, 640, Mbase, nbase, smem_u32(sh));
}

// ---------------- fused attention + out-proj + residual + LayerNorm ----------------
#define AROWW 68                                  // words per smem row (136 halves)
#define ATTN_SMEM ((160 + 128) * AROWW * 4)       // 78336 bytes

__global__ void __launch_bounds__(256, 2) attn_kernel(
    const float* __restrict__ out_w, const float* __restrict__ out_b,
    const float* __restrict__ ln_g, const float* __restrict__ ln_b) {
    extern __shared__ uint32_t smw[];
    uint32_t* s_ctx = smw;                 // [160][AROWW] words (fp16 ctx)
    uint32_t* s_w = smw + 160 * AROWW;     // [128][AROWW] words (fp16 out_w)

    int tid = threadIdx.x, warp = tid >> 5, lane = tid & 31;
    int S0 = blockIdx.x * 32;
    uint32_t ctx_u = smem_u32(s_ctx);
    uint32_t w_u = smem_u32(s_w);

    // stage out_w -> fp16 smem
    for (int idx = tid; idx < 128 * 16; idx += 256) {
        int r = idx >> 4;
        int c8 = (idx & 15) * 8;
        const float4* p = reinterpret_cast<const float4*>(out_w + (size_t)r * 128 + c8);
        float4 a = p[0], b = p[1];
        __half2 h0 = __floats2half2_rn(a.x, a.y);
        __half2 h1 = __floats2half2_rn(a.z, a.w);
        __half2 h2 = __floats2half2_rn(b.x, b.y);
        __half2 h3 = __floats2half2_rn(b.z, b.w);
        uint4 o;
        o.x = *reinterpret_cast<uint32_t*>(&h0);
        o.y = *reinterpret_cast<uint32_t*>(&h1);
        o.z = *reinterpret_cast<uint32_t*>(&h2);
        o.w = *reinterpret_cast<uint32_t*>(&h3);
        *reinterpret_cast<uint4*>(s_w + r * AROWW + (c8 >> 1)) = o;
    }

    // softmax + ctx (fp16 inputs, fp32 math), 4 samples per warp
#pragma unroll
    for (int t = 0; t < 4; t++) {
        int sl = warp * 4 + t;
        int s = S0 + sl;
        const __half* rb = g_xqkvh + (size_t)s * (NMOD * 512);
        float attn[5] = {0.f, 0.f, 0.f, 0.f, 0.f};
        if (lane < 20) {
            int h = lane / 5, i = lane % 5;
            float qv[32];
            {
                const uint4* qp = reinterpret_cast<const uint4*>(rb + i * 512 + 128 + h * 32);
#pragma unroll
                for (int u = 0; u < 4; u++) {
                    uint4 w = qp[u];
                    const uint32_t ww[4] = {w.x, w.y, w.z, w.w};
#pragma unroll
                    for (int e = 0; e < 4; e++) {
                        float2 f = __half22float2(*reinterpret_cast<const __half2*>(&ww[e]));
                        qv[u * 8 + e * 2] = f.x; qv[u * 8 + e * 2 + 1] = f.y;
                    }
                }
            }
            float sc[5];
#pragma unroll
            for (int j = 0; j < 5; j++) {
                const uint4* kp = reinterpret_cast<const uint4*>(rb + j * 512 + 256 + h * 32);
                float a = 0.f;
#pragma unroll
                for (int u = 0; u < 4; u++) {
                    uint4 w = kp[u];
                    const uint32_t ww[4] = {w.x, w.y, w.z, w.w};
#pragma unroll
                    for (int e = 0; e < 4; e++) {
                        float2 f = __half22float2(*reinterpret_cast<const __half2*>(&ww[e]));
                        a += qv[u * 8 + e * 2] * f.x + qv[u * 8 + e * 2 + 1] * f.y;
                    }
                }
                sc[j] = a * 0.17677669529663687f;   // 1/sqrt(32)
            }
            float mx = sc[0];
#pragma unroll
            for (int j = 1; j < 5; j++) mx = fmaxf(mx, sc[j]);
            float den = 0.f;
#pragma unroll
            for (int j = 0; j < 5; j++) { attn[j] = __expf(sc[j] - mx); den += attn[j]; }
            float inv = 1.f / den;
#pragma unroll
            for (int j = 0; j < 5; j++) attn[j] *= inv;
        }
        __syncwarp();
        int h2 = lane >> 3;
#pragma unroll
        for (int i = 0; i < 5; i++) {
            float a0 = 0.f, a1 = 0.f, a2 = 0.f, a3 = 0.f;
#pragma unroll
            for (int j = 0; j < 5; j++) {
                float a = __shfl_sync(0xffffffffu, attn[j], h2 * 5 + i);
                uint2 w = *reinterpret_cast<const uint2*>(rb + j * 512 + 384 + lane * 4);
                float2 f0 = __half22float2(*reinterpret_cast<const __half2*>(&w.x));
                float2 f1 = __half22float2(*reinterpret_cast<const __half2*>(&w.y));
                a0 += a * f0.x; a1 += a * f0.y; a2 += a * f1.x; a3 += a * f1.y;
            }
            __half2 h0 = __floats2half2_rn(a0, a1);
            __half2 h1 = __floats2half2_rn(a2, a3);
            *reinterpret_cast<uint2*>(s_ctx + (sl * 5 + i) * AROWW + lane * 2) =
                make_uint2(*reinterpret_cast<uint32_t*>(&h0), *reinterpret_cast<uint32_t*>(&h1));
        }
    }
    __syncthreads();

    // out-projection (ldmatrix + fp16 mma) + bias + residual + LayerNorm in registers
    int lr = lane >> 2, lc = lane & 3;
    uint32_t aoffb = ((uint32_t)(((lane & 15)) * AROWW + ((lane >> 4) << 2))) << 2;
    uint32_t boffb = ((uint32_t)(((((lane >> 4) & 1) << 3) + (lane & 7)) * AROWW
                                 + (((lane >> 3) & 1) << 2))) << 2;
    for (int strip = warp; strip < 10; strip += 8) {
        float acc[16][4];
#pragma unroll
        for (int nf = 0; nf < 16; nf++) {
            acc[nf][0] = 0.f; acc[nf][1] = 0.f; acc[nf][2] = 0.f; acc[nf][3] = 0.f;
        }
        uint32_t abase = ctx_u + (uint32_t)(strip * 16 * AROWW * 4) + aoffb;
#pragma unroll
        for (int ks = 0; ks < 8; ks++) {
            uint32_t af[4];
            ldsm4(af[0], af[1], af[2], af[3], abase + ks * 32);
#pragma unroll
            for (int p = 0; p < 8; p++) {
                uint32_t b0, b1, b2, b3;
                ldsm4(b0, b1, b2, b3, w_u + (uint32_t)(p * 16 * AROWW * 4) + boffb + ks * 32);
                mma_f16(acc[2 * p], af, b0, b1);
                mma_f16(acc[2 * p + 1], af, b2, b3);
            }
        }
        // residual + LN for the two rows owned by this thread
        int tr0 = strip * 16 + lr;
        int s0i = (S0 * 5 + tr0) / 5, tk0 = (S0 * 5 + tr0) % 5;
        int s1i = (S0 * 5 + tr0 + 8) / 5, tk1 = (S0 * 5 + tr0 + 8) % 5;
        const __half* x0 = g_xqkvh + (size_t)s0i * (NMOD * 512) + tk0 * 512;
        const __half* x1 = g_xqkvh + (size_t)s1i * (NMOD * 512) + tk1 * 512;
        float s0 = 0.f, q0 = 0.f, s1 = 0.f, q1 = 0.f;
#pragma unroll
        for (int nf = 0; nf < 16; nf++) {
            int col = nf * 8 + lc * 2;
            float2 ob = *reinterpret_cast<const float2*>(out_b + col);
            uint32_t xw0 = *reinterpret_cast<const uint32_t*>(x0 + col);
            uint32_t xw1 = *reinterpret_cast<const uint32_t*>(x1 + col);
            float2 xv0 = __half22float2(*reinterpret_cast<const __half2*>(&xw0));
            float2 xv1 = __half22float2(*reinterpret_cast<const __half2*>(&xw1));
            acc[nf][0] += ob.x + xv0.x;
            acc[nf][1] += ob.y + xv0.y;
            acc[nf][2] += ob.x + xv1.x;
            acc[nf][3] += ob.y + xv1.y;
            s0 += acc[nf][0] + acc[nf][1];
            q0 += acc[nf][0] * acc[nf][0] + acc[nf][1] * acc[nf][1];
            s1 += acc[nf][2] + acc[nf][3];
            q1 += acc[nf][2] * acc[nf][2] + acc[nf][3] * acc[nf][3];
        }
#pragma unroll
        for (int o = 1; o <= 2; o <<= 1) {
            s0 += __shfl_xor_sync(0xffffffffu, s0, o);
            q0 += __shfl_xor_sync(0xffffffffu, q0, o);
            s1 += __shfl_xor_sync(0xffffffffu, s1, o);
            q1 += __shfl_xor_sync(0xffffffffu, q1, o);
        }
        float mu0 = s0 * (1.f / 128.f);
        float rs0 = rsqrtf(q0 * (1.f / 128.f) - mu0 * mu0 + 1e-5f);
        float mu1 = s1 * (1.f / 128.f);
        float rs1 = rsqrtf(q1 * (1.f / 128.f) - mu1 * mu1 + 1e-5f);
        __half* y0 = g_yh + ((size_t)S0 * 5 + tr0) * 128;
        __half* y1 = g_yh + ((size_t)S0 * 5 + tr0 + 8) * 128;
#pragma unroll
        for (int nf = 0; nf < 16; nf++) {
            int col = nf * 8 + lc * 2;
            float2 gg = *reinterpret_cast<const float2*>(ln_g + col);
            float2 bb = *reinterpret_cast<const float2*>(ln_b + col);
            __half2 h0 = __floats2half2_rn((acc[nf][0] - mu0) * rs0 * gg.x + bb.x,
                                           (acc[nf][1] - mu0) * rs0 * gg.y + bb.y);
            __half2 h1 = __floats2half2_rn((acc[nf][2] - mu1) * rs1 * gg.x + bb.x,
                                           (acc[nf][3] - mu1) * rs1 * gg.y + bb.y);
            *reinterpret_cast<uint32_t*>(y0 + col) = *reinterpret_cast<uint32_t*>(&h0);
            *reinterpret_cast<uint32_t*>(y1 + col) = *reinterpret_cast<uint32_t*>(&h1);
        }
    }
}

// ---------------- launcher ----------------
extern "C" void kernel_launch(void* const* d_in, const int* in_sizes, int n_in,
                              void* d_out, int out_size) {
    const float* cat    = (const float*)d_in[0];
    const float* menu   = (const float*)d_in[1];
    const float* diner  = (const float*)d_in[2];
    const float* price  = (const float*)d_in[3];
    const float* review = (const float*)d_in[4];
    const float* Wc = (const float*)d_in[5];  const float* bc = (const float*)d_in[6];
    const float* Wm = (const float*)d_in[7];  const float* bm = (const float*)d_in[8];
    const float* Wd = (const float*)d_in[9];  const float* bd = (const float*)d_in[10];
    const float* Wp = (const float*)d_in[11]; const float* bp = (const float*)d_in[12];
    const float* Wr = (const float*)d_in[13]; const float* br = (const float*)d_in[14];
    const float* in_w = (const float*)d_in[15];  const float* in_b = (const float*)d_in[16];
    const float* out_w = (const float*)d_in[17]; const float* out_b = (const float*)d_in[18];
    const float* ln_g = (const float*)d_in[19];  const float* ln_b = (const float*)d_in[20];
    const float* fus_w = (const float*)d_in[21]; const float* fus_b = (const float*)d_in[22];

    int B = in_sizes[0] / 128;

    cudaFuncSetAttribute(gemmA_kernel, cudaFuncAttributeMaxDynamicSharedMemorySize, GEMM_SMEM);
    cudaFuncSetAttribute(gemmF_kernel, cudaFuncAttributeMaxDynamicSharedMemorySize, GEMM_SMEM);
    cudaFuncSetAttribute(attn_kernel, cudaFuncAttributeMaxDynamicSharedMemorySize, ATTN_SMEM);

    size_t off0 = 0;
    size_t off1 = off0 + (size_t)B * 128;
    size_t off2 = off1 + (size_t)B * 256;
    size_t off3 = off2 + (size_t)B * 64;
    size_t off4 = off3 + (size_t)B * 32;
    size_t off5 = off4 + (size_t)B * 512;   // fus_w

    // cvt: embeddings + fus_w -> fp16
    {
        CvtParams cp;
        cp.src[0] = cat;    cp.off[0] = off0; cp.n[0] = B * 128;
        cp.src[1] = menu;   cp.off[1] = off1; cp.n[1] = B * 256;
        cp.src[2] = diner;  cp.off[2] = off2; cp.n[2] = B * 64;
        cp.src[3] = price;  cp.off[3] = off3; cp.n[3] = B * 32;
        cp.src[4] = review; cp.off[4] = off4; cp.n[4] = B * 512;
        cp.src[5] = fus_w;  cp.off[5] = off5; cp.n[5] = 992 * 640;
        int maxn = B * 512;
        dim3 grid((maxn / 8 + 255) / 256, 6);
        cvt_kernel<<<grid, 256>>>(cp);
    }

    // prep: merged fp16 weights + fp32 biases
    {
        dim3 grid((512 * 512) / 256, 5);
        prep_all_kernel<<<grid, 256>>>(Wc, bc, Wm, bm, Wd, bd, Wp, bp, Wr, br,
                                       in_w, in_b);
    }

    // phase A: 5 modality GEMMs -> g_xqkvh (fp16)
    {
        GemmAParams p;
        p.aoff[0] = off0; p.K[0] = 128; p.woff[0] = 0;
        p.aoff[1] = off1; p.K[1] = 256; p.woff[1] = 512 * 128;
        p.aoff[2] = off2; p.K[2] = 64;  p.woff[2] = 512 * 384;
        p.aoff[3] = off3; p.K[3] = 32;  p.woff[3] = 512 * 448;
        p.aoff[4] = off4; p.K[4] = 512; p.woff[4] = 512 * 480;
        dim3 grid(4, B / 128, 5);
        gemmA_kernel<<<grid, 256, GEMM_SMEM>>>(p);
    }

    attn_kernel<<<B / 32, 256, ATTN_SMEM>>>(out_w, out_b, ln_g, ln_b);

    // fusion GEMM -> d_out
    {
        dim3 grid(8, B / 128);
        gemmF_kernel<<<grid, 256, GEMM_SMEM>>>(off5, fus_b, (float*)d_out);
    }
}